// round 5
// baseline (speedup 1.0000x reference)
#include <cuda_runtime.h>

// Soft quantizer forward == hard nearest-level quantization (straight-through).
// levels[k] = -1 + k*(2/24), k = 0..24.
//
// Steady-state optimization: pin the 67MB input in L2 (256-bit loads with
// L2::evict_last — the only form sm_103a ptxas accepts for the hint) and
// stream the 67MB output at evict-first priority (st.global.cs), so across
// CUDA-graph replays the input stays L2-resident and steady-state DRAM
// traffic approaches the output drain alone.

#define Z_MIN   (-1.0f)
#define STEP    (2.0f / 24.0f)
#define INVSTEP (12.0f)
#define LMAX    (24.0f)

__device__ __forceinline__ float quant1(float x) {
    float k = rintf((x - Z_MIN) * INVSTEP);
    k = fminf(fmaxf(k, 0.0f), LMAX);
    return fmaf(k, STEP, Z_MIN);
}

struct f8 { float v[8]; };

// 256-bit load, non-coherent, L2 evict_last (high retention priority).
__device__ __forceinline__ f8 ld8_evict_last(const float* p) {
    f8 r;
    asm volatile("ld.global.nc.L2::evict_last.v8.b32 "
                 "{%0,%1,%2,%3,%4,%5,%6,%7}, [%8];"
                 : "=f"(r.v[0]), "=f"(r.v[1]), "=f"(r.v[2]), "=f"(r.v[3]),
                   "=f"(r.v[4]), "=f"(r.v[5]), "=f"(r.v[6]), "=f"(r.v[7])
                 : "l"(p));
    return r;
}

// 128-bit streaming store (evict-first in L2).
__device__ __forceinline__ void st4_stream(float* p, float a, float b, float c, float d) {
    asm volatile("st.global.cs.v4.f32 [%0], {%1,%2,%3,%4};"
                 :: "l"(p), "f"(a), "f"(b), "f"(c), "f"(d)
                 : "memory");
}

// Block-tiled over float8 units: each block covers blockDim.x * 2 float8s
// (= 64B per thread). Two independent front-batched 256-bit loads per thread.
__global__ void __launch_bounds__(256) quant_kernel_v8(const float* __restrict__ in,
                                                       float* __restrict__ out,
                                                       int n8) {
    int base = blockIdx.x * (blockDim.x * 2) + threadIdx.x;
    int s = blockDim.x;

    int i0 = base;          // float8 index
    int i1 = base + s;

    if (i1 < n8) {
        f8 a = ld8_evict_last(in + (size_t)i0 * 8);
        f8 b = ld8_evict_last(in + (size_t)i1 * 8);
        #pragma unroll
        for (int j = 0; j < 8; j++) a.v[j] = quant1(a.v[j]);
        #pragma unroll
        for (int j = 0; j < 8; j++) b.v[j] = quant1(b.v[j]);
        float* o0 = out + (size_t)i0 * 8;
        float* o1 = out + (size_t)i1 * 8;
        st4_stream(o0,     a.v[0], a.v[1], a.v[2], a.v[3]);
        st4_stream(o0 + 4, a.v[4], a.v[5], a.v[6], a.v[7]);
        st4_stream(o1,     b.v[0], b.v[1], b.v[2], b.v[3]);
        st4_stream(o1 + 4, b.v[4], b.v[5], b.v[6], b.v[7]);
    } else if (i0 < n8) {
        f8 a = ld8_evict_last(in + (size_t)i0 * 8);
        #pragma unroll
        for (int j = 0; j < 8; j++) a.v[j] = quant1(a.v[j]);
        float* o0 = out + (size_t)i0 * 8;
        st4_stream(o0,     a.v[0], a.v[1], a.v[2], a.v[3]);
        st4_stream(o0 + 4, a.v[4], a.v[5], a.v[6], a.v[7]);
    }
}

__global__ void __launch_bounds__(256) quant_kernel_tail(const float* __restrict__ in,
                                                         float* __restrict__ out,
                                                         int start, int n) {
    int i = start + blockIdx.x * blockDim.x + threadIdx.x;
    if (i < n) out[i] = quant1(in[i]);
}

extern "C" void kernel_launch(void* const* d_in, const int* in_sizes, int n_in,
                              void* d_out, int out_size) {
    const float* x = (const float*)d_in[0];
    float* out = (float*)d_out;
    int n = in_sizes[0];

    int n8 = n / 8;                 // full float8 chunks
    int tail_start = n8 * 8;

    if (n8 > 0) {
        const int threads = 256;
        const int per_block = threads * 2;          // float8s per block
        int blocks = (n8 + per_block - 1) / per_block;
        quant_kernel_v8<<<blocks, threads>>>(x, out, n8);
    }
    if (tail_start < n) {
        int rem = n - tail_start;
        int threads = 256;
        int blocks = (rem + threads - 1) / threads;
        quant_kernel_tail<<<blocks, threads>>>(x, out, tail_start, n);
    }
}

// round 6
// speedup vs baseline: 1.3204x; 1.3204x over previous
#include <cuda_runtime.h>

// Soft quantizer forward == hard nearest-level quantization (straight-through).
// levels[k] = -1 + k*(2/24), k = 0..24.
//
// Pure HBM-streaming kernel. Proven-best structure (R2): block-tiled float4,
// __ldcg loads (L2-cached, skip L1) + __stcs streaming stores. This round:
// 8 front-batched float4 loads per thread (128B/thread) to cut per-byte issue
// overhead and maximize memory-level parallelism.

#define Z_MIN   (-1.0f)
#define STEP    (2.0f / 24.0f)
#define INVSTEP (12.0f)
#define LMAX    (24.0f)

__device__ __forceinline__ float quant1(float x) {
    float k = rintf((x - Z_MIN) * INVSTEP);
    k = fminf(fmaxf(k, 0.0f), LMAX);
    return fmaf(k, STEP, Z_MIN);
}

__device__ __forceinline__ float4 quant4(float4 a) {
    float4 r;
    r.x = quant1(a.x); r.y = quant1(a.y); r.z = quant1(a.z); r.w = quant1(a.w);
    return r;
}

#define TILE 8   // float4s per thread

// Each block covers blockDim.x * TILE consecutive float4s; lane stride per
// instruction is 16B -> fully coalesced LDG.128 / STG.128.
__global__ void __launch_bounds__(256) quant_kernel_v8t(const float4* __restrict__ in,
                                                        float4* __restrict__ out,
                                                        int n4) {
    int base = blockIdx.x * (blockDim.x * TILE) + threadIdx.x;
    int s = blockDim.x;

    int idx[TILE];
    #pragma unroll
    for (int j = 0; j < TILE; j++) idx[j] = base + j * s;

    if (idx[TILE - 1] < n4) {
        // fast path: all in range (every block except possibly the last)
        float4 v[TILE];
        #pragma unroll
        for (int j = 0; j < TILE; j++) v[j] = __ldcg(&in[idx[j]]);   // 8 front-batched loads
        #pragma unroll
        for (int j = 0; j < TILE; j++) v[j] = quant4(v[j]);
        #pragma unroll
        for (int j = 0; j < TILE; j++) __stcs(&out[idx[j]], v[j]);
    } else {
        #pragma unroll
        for (int j = 0; j < TILE; j++) {
            if (idx[j] < n4) __stcs(&out[idx[j]], quant4(__ldcg(&in[idx[j]])));
        }
    }
}

__global__ void __launch_bounds__(256) quant_kernel_tail(const float* __restrict__ in,
                                                         float* __restrict__ out,
                                                         int start, int n) {
    int i = start + blockIdx.x * blockDim.x + threadIdx.x;
    if (i < n) out[i] = quant1(in[i]);
}

extern "C" void kernel_launch(void* const* d_in, const int* in_sizes, int n_in,
                              void* d_out, int out_size) {
    const float* x = (const float*)d_in[0];
    float* out = (float*)d_out;
    int n = in_sizes[0];

    int n4 = n / 4;
    int tail_start = n4 * 4;

    if (n4 > 0) {
        const int threads = 256;
        const int per_block = threads * TILE;        // float4s per block
        int blocks = (n4 + per_block - 1) / per_block;
        quant_kernel_v8t<<<blocks, threads>>>((const float4*)x, (float4*)out, n4);
    }
    if (tail_start < n) {
        int rem = n - tail_start;
        int threads = 256;
        int blocks = (rem + threads - 1) / threads;
        quant_kernel_tail<<<blocks, threads>>>(x, out, tail_start, n);
    }
}